// round 15
// baseline (speedup 1.0000x reference)
#include <cuda_runtime.h>
#include <cuda_bf16.h>
#include <cstdint>

// Shapes fixed by the reference: x [8,8192,128], embed [1024,128]
#define DIM     128
#define KCODES  1024
#define NROWS   65536
#define KEXT    384          // [hi|lo|hi] x  vs  [hi|hi|lo] e  -> 3-term bf16 split
#define MROWS   128          // rows per gemm block
#define NT      64           // codes per tile
#define NTILES  (KCODES/NT)  // 16
#define TAU     0.05f        // top-2 gap below which we recompute exactly

#define ASTR    392          // padded row stride in bf16 (784 B = 4-bank shift/row)
#define SM_A    0
#define SM_B0   (MROWS*ASTR*2)            // 100352
#define SM_B1   (SM_B0 + NT*ASTR*2)       // +50176
#define SM_EN   (SM_B1 + NT*ASTR*2)       // 200704, 4 KB enorm
#define SM_RED  (SM_EN + KCODES*4)        // 204800, 3 KB reduce
#define SMEM_TOTAL (SM_RED + 128*2*12)

static const float DECAY_F = 0.99f;
static const float OMD_F   = (float)(1.0 - 0.99);
static const float EPS_F   = 1e-5f;

// ---- device scratch (no cudaMalloc allowed) ----
__device__ float g_counts[KCODES];
__device__ float g_sums[KCODES * DIM];
__device__ float g_enorm[KCODES];
__device__ float g_inv[KCODES];
__device__ __align__(16) __nv_bfloat16 g_e2[KCODES * KEXT];   // [hi|hi|lo]
__device__ int g_ind[NROWS];
__device__ int g_fix[NROWS];
__device__ int g_fix_cnt;

// ---------------------------------------------------------------------------
__device__ __forceinline__ uint32_t smem_u32(const void* p) {
    uint32_t a;
    asm("{ .reg .u64 t; cvta.to.shared.u64 t, %1; cvt.u32.u64 %0, t; }" : "=r"(a) : "l"(p));
    return a;
}
__device__ __forceinline__ void cp16(uint32_t dst, const void* src) {
    asm volatile("cp.async.cg.shared.global [%0], [%1], 16;" :: "r"(dst), "l"(src) : "memory");
}
#define CP_COMMIT() asm volatile("cp.async.commit_group;" ::: "memory")
#define CP_WAIT(n)  asm volatile("cp.async.wait_group %0;" :: "n"(n) : "memory")

// mma.sync m16n8k16 bf16 (sm_80+ PTX, valid at base sm_103 target)
__device__ __forceinline__ void mma16816(float* c, const uint32_t* a, const uint32_t* b) {
    asm volatile(
        "mma.sync.aligned.m16n8k16.row.col.f32.bf16.bf16.f32 "
        "{%0,%1,%2,%3}, {%4,%5,%6,%7}, {%8,%9}, {%0,%1,%2,%3};"
        : "+f"(c[0]), "+f"(c[1]), "+f"(c[2]), "+f"(c[3])
        : "r"(a[0]), "r"(a[1]), "r"(a[2]), "r"(a[3]), "r"(b[0]), "r"(b[1]));
}

// ---------------------------------------------------------------------------
// k_init: enorm, zero scratch, embed -> [hi|hi|lo] bf16 split
// ---------------------------------------------------------------------------
__global__ void k_init(const float* __restrict__ embed) {
    int k = blockIdx.x, t = threadIdx.x;
    float v = embed[k * DIM + t];
    float p = v * v;
#pragma unroll
    for (int off = 16; off > 0; off >>= 1) p += __shfl_down_sync(0xffffffffu, p, off);
    __shared__ float s[4];
    if ((t & 31) == 0) s[t >> 5] = p;
    __syncthreads();
    if (t == 0) { g_enorm[k] = s[0] + s[1] + s[2] + s[3]; g_counts[k] = 0.0f; }
    if (k == 0 && t == 0) g_fix_cnt = 0;
    g_sums[(size_t)k * DIM + t] = 0.0f;
    __nv_bfloat16 h = __float2bfloat16(v);
    __nv_bfloat16 l = __float2bfloat16(v - __bfloat162float(h));
    g_e2[k * KEXT + t]       = h;
    g_e2[k * KEXT + 128 + t] = h;
    g_e2[k * KEXT + 256 + t] = l;
}

// ---------------------------------------------------------------------------
// k_gemm: bf16 mma.sync distance GEMM + per-row top-2 argmax
// 512 blocks x 256 thr. Warp (wm 0..3, wn 0..1) owns rows wm*32..+31,
// codes wn*32..+31 per tile. A resident in smem, B double-buffered cp.async.
// ---------------------------------------------------------------------------
__global__ __launch_bounds__(256, 1)
void k_gemm(const float* __restrict__ x) {
    extern __shared__ unsigned char sm[];
    __nv_bfloat16* As = (__nv_bfloat16*)(sm + SM_A);
    float* enorm_s = (float*)(sm + SM_EN);
    float* redS  = (float*)(sm + SM_RED);
    int*   redI  = (int*)(sm + SM_RED + 1024);
    float* redS2 = (float*)(sm + SM_RED + 2048);

    const int tid  = threadIdx.x;
    const int lane = tid & 31;
    const int wid  = tid >> 5;
    const int wm   = wid >> 1;
    const int wn   = wid & 1;
    const long long rowBase = (long long)blockIdx.x * MROWS;

    // enorm -> smem
#pragma unroll
    for (int m = 0; m < 4; m++)
        enorm_s[tid + m * 256] = g_enorm[tid + m * 256];

    // A: load x [128 x 128] f32, split into [hi|lo|hi] bf16 rows of ASTR
    {
        const float4* xg = (const float4*)(x + rowBase * DIM);
#pragma unroll
        for (int m = 0; m < 16; m++) {
            int flat = tid + m * 256;         // 4096 float4
            int r = flat >> 5, c4 = flat & 31;
            float4 v = xg[flat];
            union { __nv_bfloat16 h[4]; unsigned long long u; } H, L;
            H.h[0] = __float2bfloat16(v.x); L.h[0] = __float2bfloat16(v.x - __bfloat162float(H.h[0]));
            H.h[1] = __float2bfloat16(v.y); L.h[1] = __float2bfloat16(v.y - __bfloat162float(H.h[1]));
            H.h[2] = __float2bfloat16(v.z); L.h[2] = __float2bfloat16(v.z - __bfloat162float(H.h[2]));
            H.h[3] = __float2bfloat16(v.w); L.h[3] = __float2bfloat16(v.w - __bfloat162float(H.h[3]));
            __nv_bfloat16* rp = As + (size_t)r * ASTR;
            *(unsigned long long*)(rp + c4 * 4)       = H.u;   // hi  @ k 0..127
            *(unsigned long long*)(rp + 128 + c4 * 4) = L.u;   // lo  @ k 128..255
            *(unsigned long long*)(rp + 256 + c4 * 4) = H.u;   // hi  @ k 256..383
        }
    }

    // B prefetch helper (lambda-free): tile t into buffer buf
    const uint32_t smb = smem_u32(sm);
#define PREFETCH_B(t, buf) do {                                               \
        const __nv_bfloat16* eb = g_e2 + (size_t)(t) * NT * KEXT;             \
        uint32_t sb = smb + ((buf) ? SM_B1 : SM_B0);                          \
        _Pragma("unroll")                                                     \
        for (int m = 0; m < 12; m++) {                                        \
            int flat = tid + m * 256;       /* 3072 chunks of 16 B */         \
            int r = flat / 48, ch = flat % 48;                                \
            cp16(sb + (uint32_t)(r * (ASTR * 2) + ch * 16),                   \
                 eb + (size_t)r * KEXT + ch * 8);                             \
        }                                                                     \
        CP_COMMIT();                                                          \
    } while (0)

    PREFETCH_B(0, 0);

    // fragment base offsets (bf16 units)
    const uint32_t aoff = (uint32_t)((wm * 32 + (lane >> 2)) * ASTR + (lane & 3) * 2);
    const uint32_t boff0 = (uint32_t)(((lane >> 2)) * ASTR + (lane & 3) * 2);

    float bs[2][2], ss[2][2];
    int   bi[2][2];
#pragma unroll
    for (int a = 0; a < 2; a++)
#pragma unroll
        for (int b = 0; b < 2; b++) { bs[a][b] = -3.4e38f; ss[a][b] = -3.4e38f; bi[a][b] = 0; }

    __syncthreads();   // A + enorm visible (prefetch outstanding)

    for (int t = 0; t < NTILES; t++) {
        if (t + 1 < NTILES) { PREFETCH_B(t + 1, (t + 1) & 1); CP_WAIT(1); }
        else                { CP_WAIT(0); }
        __syncthreads();   // tile t data ready in buf t&1

        const __nv_bfloat16* Bs = (const __nv_bfloat16*)(sm + ((t & 1) ? SM_B1 : SM_B0));

        float acc[2][4][4];
#pragma unroll
        for (int mi = 0; mi < 2; mi++)
#pragma unroll
            for (int ni = 0; ni < 4; ni++)
#pragma unroll
                for (int e = 0; e < 4; e++) acc[mi][ni][e] = 0.0f;

#pragma unroll
        for (int ks = 0; ks < KEXT / 16; ks++) {
            const int k0 = ks * 16;
            uint32_t a[2][4], b[4][2];
#pragma unroll
            for (int mi = 0; mi < 2; mi++) {
                uint32_t base = aoff + mi * (16 * ASTR) + k0;
                a[mi][0] = *(const uint32_t*)(As + base);
                a[mi][1] = *(const uint32_t*)(As + base + 8 * ASTR);
                a[mi][2] = *(const uint32_t*)(As + base + 8);
                a[mi][3] = *(const uint32_t*)(As + base + 8 * ASTR + 8);
            }
#pragma unroll
            for (int ni = 0; ni < 4; ni++) {
                uint32_t base = boff0 + (uint32_t)((wn * 32 + ni * 8) * ASTR) + k0;
                b[ni][0] = *(const uint32_t*)(Bs + base);
                b[ni][1] = *(const uint32_t*)(Bs + base + 8);
            }
#pragma unroll
            for (int mi = 0; mi < 2; mi++)
#pragma unroll
                for (int ni = 0; ni < 4; ni++)
                    mma16816(acc[mi][ni], a[mi], b[ni]);
        }

        // scores: D[r][c] -> 2*dot - enorm ; top-2 per owned row, ascending code order
        const int cb = t * NT + wn * 32 + (lane & 3) * 2;
#pragma unroll
        for (int ni = 0; ni < 4; ni++) {
            const int c0 = cb + ni * 8;
            const float e0 = enorm_s[c0], e1 = enorm_s[c0 + 1];
#pragma unroll
            for (int mi = 0; mi < 2; mi++) {
#pragma unroll
                for (int rh = 0; rh < 2; rh++) {
                    float s0 = fmaf(acc[mi][ni][rh * 2 + 0], 2.0f, -e0);
                    float s1 = fmaf(acc[mi][ni][rh * 2 + 1], 2.0f, -e1);
                    if (s0 > ss[mi][rh]) {
                        if (s0 > bs[mi][rh]) { ss[mi][rh] = bs[mi][rh]; bs[mi][rh] = s0; bi[mi][rh] = c0; }
                        else ss[mi][rh] = s0;
                    }
                    if (s1 > ss[mi][rh]) {
                        if (s1 > bs[mi][rh]) { ss[mi][rh] = bs[mi][rh]; bs[mi][rh] = s1; bi[mi][rh] = c0 + 1; }
                        else ss[mi][rh] = s1;
                    }
                }
            }
        }
        __syncthreads();   // done with buf t&1 before its re-prefetch next iter
    }

    // merge across the 4 lanes of each quad (same rows)
#pragma unroll
    for (int off = 1; off <= 2; off <<= 1) {
#pragma unroll
        for (int mi = 0; mi < 2; mi++)
#pragma unroll
            for (int rh = 0; rh < 2; rh++) {
                float obs = __shfl_xor_sync(0xffffffffu, bs[mi][rh], off);
                int   obi = __shfl_xor_sync(0xffffffffu, bi[mi][rh], off);
                float oss = __shfl_xor_sync(0xffffffffu, ss[mi][rh], off);
                float loser = fminf(bs[mi][rh], obs);
                float nss = fmaxf(loser, fmaxf(ss[mi][rh], oss));
                if (obs > bs[mi][rh] || (obs == bs[mi][rh] && obi < bi[mi][rh])) {
                    bs[mi][rh] = obs; bi[mi][rh] = obi;
                }
                ss[mi][rh] = nss;
            }
    }
    if ((lane & 3) == 0) {
#pragma unroll
        for (int mi = 0; mi < 2; mi++)
#pragma unroll
            for (int rh = 0; rh < 2; rh++) {
                int r = wm * 32 + mi * 16 + rh * 8 + (lane >> 2);
                redS[r * 2 + wn]  = bs[mi][rh];
                redI[r * 2 + wn]  = bi[mi][rh];
                redS2[r * 2 + wn] = ss[mi][rh];
            }
    }
    __syncthreads();
    if (tid < MROWS) {
        float b0 = redS[tid * 2], b1 = redS[tid * 2 + 1];
        int   i0 = redI[tid * 2], i1 = redI[tid * 2 + 1];
        float s0 = redS2[tid * 2], s1 = redS2[tid * 2 + 1];
        float loser = fminf(b0, b1);
        float sec = fmaxf(loser, fmaxf(s0, s1));
        float best = b0; int bidx = i0;
        if (b1 > b0 || (b1 == b0 && i1 < i0)) { best = b1; bidx = i1; }
        g_ind[rowBase + tid] = bidx;
        if (best - sec < TAU) {
            int p = atomicAdd(&g_fix_cnt, 1);
            g_fix[p] = (int)(rowBase + tid);
        }
    }
}

// ---------------------------------------------------------------------------
// k_fixup: exact fp32 re-argmax for rows whose approx top-2 gap < TAU
// ---------------------------------------------------------------------------
__global__ __launch_bounds__(128) void k_fixup(const float* __restrict__ x,
                                               const float* __restrict__ embed) {
    __shared__ float xrow[DIM];
    __shared__ float sS[128];
    __shared__ int   sI[128];
    int cnt = g_fix_cnt;
    int t = threadIdx.x;
    for (int j = blockIdx.x; j < cnt; j += gridDim.x) {
        int row = g_fix[j];
        xrow[t] = x[(size_t)row * DIM + t];
        __syncthreads();
        float best = -3.4e38f; int bidx = 0;
        for (int cc = 0; cc < 8; cc++) {
            int code = t + cc * 128;
            const float* er = embed + (size_t)code * DIM;
            float dot = 0.0f;
#pragma unroll 16
            for (int d = 0; d < DIM; d++) dot = fmaf(xrow[d], er[d], dot);
            float sc = 2.0f * dot - g_enorm[code];
            if (sc > best || (sc == best && code < bidx)) { best = sc; bidx = code; }
        }
        sS[t] = best; sI[t] = bidx;
        __syncthreads();
        for (int s = 64; s > 0; s >>= 1) {
            if (t < s) {
                float o = sS[t + s]; int oi = sI[t + s];
                if (o > sS[t] || (o == sS[t] && oi < sI[t])) { sS[t] = o; sI[t] = oi; }
            }
            __syncthreads();
        }
        if (t == 0) g_ind[row] = sI[0];
        __syncthreads();
    }
}

// ---------------------------------------------------------------------------
// k_scatter: quantize gather + ind write + segment-sum atomics. 64 rows/block.
// ---------------------------------------------------------------------------
__global__ __launch_bounds__(128) void k_scatter(const float* __restrict__ x,
                                                 const float* __restrict__ embed,
                                                 float* __restrict__ out,
                                                 long long indOff) {
    __shared__ int best_s[64];
    const int tid = threadIdx.x;
    const long long rowBase = (long long)blockIdx.x * 64;
    if (tid < 64) best_s[tid] = g_ind[rowBase + tid];
    __syncthreads();
#pragma unroll
    for (int m = 0; m < 16; m++) {
        int flat = tid + m * 128;
        int r = flat >> 5, c = flat & 31;
        int best = best_s[r];
        float4 e4 = ((const float4*)(embed + (size_t)best * DIM))[c];
        ((float4*)(out + (rowBase + r) * DIM))[c] = e4;
        float4 xv = ((const float4*)(x + (rowBase + r) * DIM))[c];
        float* sp = g_sums + (size_t)best * DIM + c * 4;
        atomicAdd(sp + 0, xv.x);
        atomicAdd(sp + 1, xv.y);
        atomicAdd(sp + 2, xv.z);
        atomicAdd(sp + 3, xv.w);
    }
    if (tid < 64) {
        int best = best_s[tid];
        atomicAdd(&g_counts[best], 1.0f);
        out[indOff + rowBase + tid] = (float)best;
    }
}

// ---------------------------------------------------------------------------
// k_final1 / k_final2: EMA + normalization epilogues
// ---------------------------------------------------------------------------
__global__ void k_final1(const float* __restrict__ cs, float* __restrict__ out,
                         long long ncsOff) {
    __shared__ float red[KCODES];
    int k = threadIdx.x;
    float ncs = cs[k] * DECAY_F + OMD_F * g_counts[k];
    out[ncsOff + k] = ncs;
    red[k] = ncs;
    __syncthreads();
    for (int s = KCODES / 2; s > 0; s >>= 1) {
        if (k < s) red[k] += red[k + s];
        __syncthreads();
    }
    float total    = red[0];
    float smoothed = (ncs + EPS_F) / (total + (float)KCODES * EPS_F);
    g_inv[k] = 1.0f / (smoothed * total);
}

__global__ void k_final2(const float* __restrict__ ea, float* __restrict__ out,
                         long long neaOff, long long neOff) {
    int i = blockIdx.x * blockDim.x + threadIdx.x;
    float nea = ea[i] * DECAY_F + OMD_F * g_sums[i];
    out[neaOff + i] = nea;
    out[neOff + i]  = nea * g_inv[i >> 7];
}

// ---------------------------------------------------------------------------
extern "C" void kernel_launch(void* const* d_in, const int* in_sizes, int n_in,
                              void* d_out, int out_size) {
    const float* x     = (const float*)d_in[0];
    const float* embed = (const float*)d_in[1];
    const float* cs    = (const float*)d_in[2];
    const float* ea    = (const float*)d_in[3];
    float* out = (float*)d_out;

    const long long N = in_sizes[0] / DIM;            // 65536 rows
    const long long indOff = N * DIM;
    const long long ncsOff = indOff + N;
    const long long neaOff = ncsOff + KCODES;
    const long long neOff  = neaOff + (long long)KCODES * DIM;

    static bool attr_set = false;
    if (!attr_set) {
        cudaFuncSetAttribute(k_gemm, cudaFuncAttributeMaxDynamicSharedMemorySize, SMEM_TOTAL);
        attr_set = true;
    }

    k_init<<<KCODES, DIM>>>(embed);
    k_gemm<<<(unsigned)(N / MROWS), 256, SMEM_TOTAL>>>(x);
    k_fixup<<<128, 128>>>(x, embed);
    k_scatter<<<(unsigned)(N / 64), 128>>>(x, embed, out, indOff);
    k_final1<<<1, KCODES>>>(cs, out, ncsOff);
    k_final2<<<KCODES * DIM / 256, 256>>>(ea, out, neaOff, neOff);
}

// round 16
// speedup vs baseline: 2.3570x; 2.3570x over previous
#include <cuda_runtime.h>
#include <cuda_bf16.h>
#include <cstdint>

// Shapes fixed by the reference: x [8,8192,128], embed [1024,128]
#define DIM     128
#define KCODES  1024
#define NROWS   65536
#define MROWS   128          // rows per gemm block
#define NT      64           // codes per tile
#define NTILES  (KCODES/NT)  // 16
#define TAU     0.8f         // top-2 gap below which row goes to exact fixup

#define ASTR    136          // padded row stride in bf16 (272 B = 4-bank shift/row)
#define SM_A    0
#define A_BYTES (MROWS*ASTR*2)            // 34816
#define SM_B0   (A_BYTES)
#define B_BYTES (NT*ASTR*2)               // 17408
#define SM_B1   (SM_B0 + B_BYTES)
#define SM_EN   (SM_B1 + B_BYTES)         // 69632
#define SM_RED  (SM_EN + KCODES*4)        // 73728 : redS|redI|redS2 (3 KB)
#define SM_BEST (SM_RED + 3072)           // 76800 : per-row best idx (512 B)
#define SM_CONF (SM_BEST + 512)           // 77312 : per-row confident flag
#define SMEM_TOTAL (SM_CONF + 512)        // 77824 -> 2 blocks/SM

static const float DECAY_F = 0.99f;
static const float OMD_F   = (float)(1.0 - 0.99);
static const float EPS_F   = 1e-5f;

// ---- device scratch (no cudaMalloc allowed) ----
__device__ float g_counts[KCODES];
__device__ float g_sums[KCODES * DIM];
__device__ float g_enorm[KCODES];
__device__ float g_inv[KCODES];
__device__ __align__(16) __nv_bfloat16 g_e1[KCODES * DIM];   // bf16(embed)
__device__ int g_fix[NROWS];
__device__ int g_fix_cnt;

// ---------------------------------------------------------------------------
__device__ __forceinline__ uint32_t smem_u32(const void* p) {
    uint32_t a;
    asm("{ .reg .u64 t; cvta.to.shared.u64 t, %1; cvt.u32.u64 %0, t; }" : "=r"(a) : "l"(p));
    return a;
}
__device__ __forceinline__ void cp16(uint32_t dst, const void* src) {
    asm volatile("cp.async.cg.shared.global [%0], [%1], 16;" :: "r"(dst), "l"(src) : "memory");
}
#define CP_COMMIT() asm volatile("cp.async.commit_group;" ::: "memory")
#define CP_WAIT(n)  asm volatile("cp.async.wait_group %0;" :: "n"(n) : "memory")

// mma.sync m16n8k16 bf16 (sm_80+ PTX, valid at base sm_103 target)
__device__ __forceinline__ void mma16816(float* c, const uint32_t* a, const uint32_t* b) {
    asm volatile(
        "mma.sync.aligned.m16n8k16.row.col.f32.bf16.bf16.f32 "
        "{%0,%1,%2,%3}, {%4,%5,%6,%7}, {%8,%9}, {%0,%1,%2,%3};"
        : "+f"(c[0]), "+f"(c[1]), "+f"(c[2]), "+f"(c[3])
        : "r"(a[0]), "r"(a[1]), "r"(a[2]), "r"(a[3]), "r"(b[0]), "r"(b[1]));
}

// ---------------------------------------------------------------------------
// k_init: enorm (fp32 exact), zero scratch, embed -> bf16
// ---------------------------------------------------------------------------
__global__ void k_init(const float* __restrict__ embed) {
    int k = blockIdx.x, t = threadIdx.x;
    float v = embed[k * DIM + t];
    float p = v * v;
#pragma unroll
    for (int off = 16; off > 0; off >>= 1) p += __shfl_down_sync(0xffffffffu, p, off);
    __shared__ float s[4];
    if ((t & 31) == 0) s[t >> 5] = p;
    __syncthreads();
    if (t == 0) { g_enorm[k] = s[0] + s[1] + s[2] + s[3]; g_counts[k] = 0.0f; }
    if (k == 0 && t == 0) g_fix_cnt = 0;
    g_sums[(size_t)k * DIM + t] = 0.0f;
    g_e1[k * DIM + t] = __float2bfloat16(v);
}

// ---------------------------------------------------------------------------
// k_gemm: bf16 mma.sync distance GEMM (K=128) + top-2 argmax + confident scatter
// 512 blocks x 256 thr, 2 blocks/SM. Warp (wm 0..3, wn 0..1): rows wm*32..+31,
// codes wn*32..+31 per 64-code tile. A resident smem, B double-buffer cp.async.
// ---------------------------------------------------------------------------
__global__ __launch_bounds__(256, 2)
void k_gemm(const float* __restrict__ x, const float* __restrict__ embed,
            float* __restrict__ out, long long indOff) {
    extern __shared__ unsigned char sm[];
    __nv_bfloat16* As = (__nv_bfloat16*)(sm + SM_A);
    float* enorm_s = (float*)(sm + SM_EN);
    float* redS  = (float*)(sm + SM_RED);
    int*   redI  = (int*)(sm + SM_RED + 1024);
    float* redS2 = (float*)(sm + SM_RED + 2048);
    int*   best_s = (int*)(sm + SM_BEST);
    int*   conf_s = (int*)(sm + SM_CONF);

    const int tid  = threadIdx.x;
    const int lane = tid & 31;
    const int wid  = tid >> 5;
    const int wm   = wid >> 1;
    const int wn   = wid & 1;
    const long long rowBase = (long long)blockIdx.x * MROWS;

#pragma unroll
    for (int m = 0; m < 4; m++)
        enorm_s[tid + m * 256] = g_enorm[tid + m * 256];

    // A: x [128 x 128] f32 -> bf16 hi rows (stride ASTR)
    {
        const float4* xg = (const float4*)(x + rowBase * DIM);
#pragma unroll
        for (int m = 0; m < 16; m++) {
            int flat = tid + m * 256;           // 4096 float4
            int r = flat >> 5, c4 = flat & 31;
            float4 v = xg[flat];
            union { __nv_bfloat16 h[4]; unsigned long long u; } H;
            H.h[0] = __float2bfloat16(v.x);
            H.h[1] = __float2bfloat16(v.y);
            H.h[2] = __float2bfloat16(v.z);
            H.h[3] = __float2bfloat16(v.w);
            *(unsigned long long*)(As + (size_t)r * ASTR + c4 * 4) = H.u;
        }
    }

    const uint32_t smb = smem_u32(sm);
#define PREFETCH_B(t, buf) do {                                               \
        const __nv_bfloat16* eb = g_e1 + (size_t)(t) * NT * DIM;              \
        uint32_t sb = smb + ((buf) ? SM_B1 : SM_B0);                          \
        _Pragma("unroll")                                                     \
        for (int m = 0; m < 4; m++) {                                         \
            int flat = tid + m * 256;        /* 1024 chunks of 16 B */        \
            int r = flat >> 4, ch = flat & 15;                                \
            cp16(sb + (uint32_t)(r * (ASTR * 2) + ch * 16),                   \
                 eb + (size_t)r * DIM + ch * 8);                              \
        }                                                                     \
        CP_COMMIT();                                                          \
    } while (0)

    PREFETCH_B(0, 0);

    const uint32_t aoff  = (uint32_t)((wm * 32 + (lane >> 2)) * ASTR + (lane & 3) * 2);
    const uint32_t boff0 = (uint32_t)((lane >> 2) * ASTR + (lane & 3) * 2);

    float bs[2][2], ss[2][2];
    int   bi[2][2];
#pragma unroll
    for (int a = 0; a < 2; a++)
#pragma unroll
        for (int b = 0; b < 2; b++) { bs[a][b] = -3.4e38f; ss[a][b] = -3.4e38f; bi[a][b] = 0; }

    __syncthreads();

    for (int t = 0; t < NTILES; t++) {
        if (t + 1 < NTILES) { PREFETCH_B(t + 1, (t + 1) & 1); CP_WAIT(1); }
        else                { CP_WAIT(0); }
        __syncthreads();

        const __nv_bfloat16* Bs = (const __nv_bfloat16*)(sm + ((t & 1) ? SM_B1 : SM_B0));

        float acc[2][4][4];
#pragma unroll
        for (int mi = 0; mi < 2; mi++)
#pragma unroll
            for (int ni = 0; ni < 4; ni++)
#pragma unroll
                for (int e = 0; e < 4; e++) acc[mi][ni][e] = 0.0f;

#pragma unroll
        for (int ks = 0; ks < DIM / 16; ks++) {
            const int k0 = ks * 16;
            uint32_t a[2][4], b[4][2];
#pragma unroll
            for (int mi = 0; mi < 2; mi++) {
                uint32_t base = aoff + mi * (16 * ASTR) + k0;
                a[mi][0] = *(const uint32_t*)(As + base);
                a[mi][1] = *(const uint32_t*)(As + base + 8 * ASTR);
                a[mi][2] = *(const uint32_t*)(As + base + 8);
                a[mi][3] = *(const uint32_t*)(As + base + 8 * ASTR + 8);
            }
#pragma unroll
            for (int ni = 0; ni < 4; ni++) {
                uint32_t base = boff0 + (uint32_t)((wn * 32 + ni * 8) * ASTR) + k0;
                b[ni][0] = *(const uint32_t*)(Bs + base);
                b[ni][1] = *(const uint32_t*)(Bs + base + 8);
            }
#pragma unroll
            for (int mi = 0; mi < 2; mi++)
#pragma unroll
                for (int ni = 0; ni < 4; ni++)
                    mma16816(acc[mi][ni], a[mi], b[ni]);
        }

        const int cb = t * NT + wn * 32 + (lane & 3) * 2;
#pragma unroll
        for (int ni = 0; ni < 4; ni++) {
            const int c0 = cb + ni * 8;
            const float e0 = enorm_s[c0], e1 = enorm_s[c0 + 1];
#pragma unroll
            for (int mi = 0; mi < 2; mi++) {
#pragma unroll
                for (int rh = 0; rh < 2; rh++) {
                    float s0 = fmaf(acc[mi][ni][rh * 2 + 0], 2.0f, -e0);
                    float s1 = fmaf(acc[mi][ni][rh * 2 + 1], 2.0f, -e1);
                    if (s0 > ss[mi][rh]) {
                        if (s0 > bs[mi][rh]) { ss[mi][rh] = bs[mi][rh]; bs[mi][rh] = s0; bi[mi][rh] = c0; }
                        else ss[mi][rh] = s0;
                    }
                    if (s1 > ss[mi][rh]) {
                        if (s1 > bs[mi][rh]) { ss[mi][rh] = bs[mi][rh]; bs[mi][rh] = s1; bi[mi][rh] = c0 + 1; }
                        else ss[mi][rh] = s1;
                    }
                }
            }
        }
        __syncthreads();
    }

    // merge across the 4 lanes of each quad (same rows)
#pragma unroll
    for (int off = 1; off <= 2; off <<= 1) {
#pragma unroll
        for (int mi = 0; mi < 2; mi++)
#pragma unroll
            for (int rh = 0; rh < 2; rh++) {
                float obs = __shfl_xor_sync(0xffffffffu, bs[mi][rh], off);
                int   obi = __shfl_xor_sync(0xffffffffu, bi[mi][rh], off);
                float oss = __shfl_xor_sync(0xffffffffu, ss[mi][rh], off);
                float loser = fminf(bs[mi][rh], obs);
                float nss = fmaxf(loser, fmaxf(ss[mi][rh], oss));
                if (obs > bs[mi][rh] || (obs == bs[mi][rh] && obi < bi[mi][rh])) {
                    bs[mi][rh] = obs; bi[mi][rh] = obi;
                }
                ss[mi][rh] = nss;
            }
    }
    if ((lane & 3) == 0) {
#pragma unroll
        for (int mi = 0; mi < 2; mi++)
#pragma unroll
            for (int rh = 0; rh < 2; rh++) {
                int r = wm * 32 + mi * 16 + rh * 8 + (lane >> 2);
                redS[r * 2 + wn]  = bs[mi][rh];
                redI[r * 2 + wn]  = bi[mi][rh];
                redS2[r * 2 + wn] = ss[mi][rh];
            }
    }
    __syncthreads();
    if (tid < MROWS) {
        float b0 = redS[tid * 2], b1 = redS[tid * 2 + 1];
        int   i0 = redI[tid * 2], i1 = redI[tid * 2 + 1];
        float s0 = redS2[tid * 2], s1 = redS2[tid * 2 + 1];
        float sec  = fmaxf(fminf(b0, b1), fmaxf(s0, s1));
        float best = b0; int bidx = i0;
        if (b1 > b0 || (b1 == b0 && i1 < i0)) { best = b1; bidx = i1; }
        int conf = (best - sec) >= TAU;
        best_s[tid] = bidx;
        conf_s[tid] = conf;
        if (conf) {
            out[indOff + rowBase + tid] = (float)bidx;
            atomicAdd(&g_counts[bidx], 1.0f);
        } else {
            int p = atomicAdd(&g_fix_cnt, 1);
            g_fix[p] = (int)(rowBase + tid);
        }
    }
    __syncthreads();

    // confident-row scatter: quantize gather + segment-sum atomics
#pragma unroll
    for (int m = 0; m < 16; m++) {
        int flat = tid + m * 256;
        int r = flat >> 5, c = flat & 31;
        if (conf_s[r]) {
            int best = best_s[r];
            float4 e4 = ((const float4*)(embed + (size_t)best * DIM))[c];
            ((float4*)(out + (rowBase + r) * DIM))[c] = e4;
            float4 xv = ((const float4*)(x + (rowBase + r) * DIM))[c];
            float* sp = g_sums + (size_t)best * DIM + c * 4;
            atomicAdd(sp + 0, xv.x);
            atomicAdd(sp + 1, xv.y);
            atomicAdd(sp + 2, xv.z);
            atomicAdd(sp + 3, xv.w);
        }
    }
}

// ---------------------------------------------------------------------------
// k_fixup: exact fp32 argmax + scatter for ambiguous rows. 32 rows per block
// chunk, embed streamed via smem in 32-code tiles (tiled fp32 GEMM).
// Thread map: tx=tid&15 (codes tx,tx+16 per tile), ty=tid>>4 (rows ty,ty+16).
// ---------------------------------------------------------------------------
__global__ __launch_bounds__(256) void k_fixup(const float* __restrict__ x,
                                               const float* __restrict__ embed,
                                               float* __restrict__ out,
                                               long long indOff) {
    __shared__ float4 xs[32][33];
    __shared__ float4 es[32][33];
    __shared__ float  en_s[KCODES];
    __shared__ int    rowIds[32];
    __shared__ int    sIdx[32];

    const int tid = threadIdx.x;
    const int tx = tid & 15, ty = tid >> 4;
#pragma unroll
    for (int m = 0; m < 4; m++) en_s[tid + m * 256] = g_enorm[tid + m * 256];

    int cnt = g_fix_cnt;
    for (int base = blockIdx.x * 32; base < cnt; base += gridDim.x * 32) {
        int nrows = min(32, cnt - base);
        if (tid < nrows) rowIds[tid] = g_fix[base + tid];
        __syncthreads();
#pragma unroll
        for (int m = 0; m < 4; m++) {
            int idx = tid + m * 256;
            int r = idx >> 5, c = idx & 31;
            if (r < nrows)
                xs[r][c] = ((const float4*)(x + (size_t)rowIds[r] * DIM))[c];
        }

        float best[2] = {-3.4e38f, -3.4e38f};
        int   bidx[2] = {0, 0};

        for (int tile = 0; tile < KCODES / 32; tile++) {
            __syncthreads();
#pragma unroll
            for (int m = 0; m < 4; m++) {
                int idx = tid + m * 256;
                int r = idx >> 5, c = idx & 31;
                es[r][c] = ((const float4*)(embed + (size_t)(tile * 32 + r) * DIM))[c];
            }
            __syncthreads();

            float acc[2][2] = {{0.f, 0.f}, {0.f, 0.f}};
#pragma unroll 8
            for (int c4 = 0; c4 < 32; c4++) {
                float4 a0 = xs[ty][c4],      a1 = xs[ty + 16][c4];
                float4 b0 = es[tx][c4],      b1 = es[tx + 16][c4];
                acc[0][0] = fmaf(a0.x, b0.x, fmaf(a0.y, b0.y, fmaf(a0.z, b0.z, fmaf(a0.w, b0.w, acc[0][0]))));
                acc[0][1] = fmaf(a0.x, b1.x, fmaf(a0.y, b1.y, fmaf(a0.z, b1.z, fmaf(a0.w, b1.w, acc[0][1]))));
                acc[1][0] = fmaf(a1.x, b0.x, fmaf(a1.y, b0.y, fmaf(a1.z, b0.z, fmaf(a1.w, b0.w, acc[1][0]))));
                acc[1][1] = fmaf(a1.x, b1.x, fmaf(a1.y, b1.y, fmaf(a1.z, b1.z, fmaf(a1.w, b1.w, acc[1][1]))));
            }
#pragma unroll
            for (int j = 0; j < 2; j++) {
                int code = tile * 32 + tx + j * 16;
                float e = en_s[code];
#pragma unroll
                for (int i = 0; i < 2; i++) {
                    float sc = 2.0f * acc[i][j] - e;
                    if (sc > best[i] || (sc == best[i] && code < bidx[i])) {
                        best[i] = sc; bidx[i] = code;
                    }
                }
            }
        }
        // reduce across the 16 tx lanes
#pragma unroll
        for (int i = 0; i < 2; i++) {
            float s = best[i]; int idx = bidx[i];
#pragma unroll
            for (int off = 8; off > 0; off >>= 1) {
                float so = __shfl_down_sync(0xffffffffu, s, off, 16);
                int   io = __shfl_down_sync(0xffffffffu, idx, off, 16);
                if (so > s || (so == s && io < idx)) { s = so; idx = io; }
            }
            if (tx == 0) sIdx[ty + i * 16] = idx;
        }
        __syncthreads();

        // scatter the fixed rows
#pragma unroll
        for (int m = 0; m < 4; m++) {
            int idx = tid + m * 256;
            int r = idx >> 5, c = idx & 31;
            if (r < nrows) {
                int bestc = sIdx[r];
                long long row = rowIds[r];
                float4 e4 = ((const float4*)(embed + (size_t)bestc * DIM))[c];
                ((float4*)(out + row * DIM))[c] = e4;
                float4 xv = xs[r][c];
                float* sp = g_sums + (size_t)bestc * DIM + c * 4;
                atomicAdd(sp + 0, xv.x);
                atomicAdd(sp + 1, xv.y);
                atomicAdd(sp + 2, xv.z);
                atomicAdd(sp + 3, xv.w);
            }
        }
        if (tid < nrows) {
            int bestc = sIdx[tid];
            atomicAdd(&g_counts[bestc], 1.0f);
            out[indOff + rowIds[tid]] = (float)bestc;
        }
        __syncthreads();
    }
}

// ---------------------------------------------------------------------------
// k_final1 / k_final2: EMA + normalization epilogues
// ---------------------------------------------------------------------------
__global__ void k_final1(const float* __restrict__ cs, float* __restrict__ out,
                         long long ncsOff) {
    __shared__ float red[KCODES];
    int k = threadIdx.x;
    float ncs = cs[k] * DECAY_F + OMD_F * g_counts[k];
    out[ncsOff + k] = ncs;
    red[k] = ncs;
    __syncthreads();
    for (int s = KCODES / 2; s > 0; s >>= 1) {
        if (k < s) red[k] += red[k + s];
        __syncthreads();
    }
    float total    = red[0];
    float smoothed = (ncs + EPS_F) / (total + (float)KCODES * EPS_F);
    g_inv[k] = 1.0f / (smoothed * total);
}

__global__ void k_final2(const float* __restrict__ ea, float* __restrict__ out,
                         long long neaOff, long long neOff) {
    int i = blockIdx.x * blockDim.x + threadIdx.x;
    float nea = ea[i] * DECAY_F + OMD_F * g_sums[i];
    out[neaOff + i] = nea;
    out[neOff + i]  = nea * g_inv[i >> 7];
}

// ---------------------------------------------------------------------------
extern "C" void kernel_launch(void* const* d_in, const int* in_sizes, int n_in,
                              void* d_out, int out_size) {
    const float* x     = (const float*)d_in[0];
    const float* embed = (const float*)d_in[1];
    const float* cs    = (const float*)d_in[2];
    const float* ea    = (const float*)d_in[3];
    float* out = (float*)d_out;

    const long long N = in_sizes[0] / DIM;            // 65536 rows
    const long long indOff = N * DIM;
    const long long ncsOff = indOff + N;
    const long long neaOff = ncsOff + KCODES;
    const long long neOff  = neaOff + (long long)KCODES * DIM;

    static bool attr_set = false;
    if (!attr_set) {
        cudaFuncSetAttribute(k_gemm, cudaFuncAttributeMaxDynamicSharedMemorySize, SMEM_TOTAL);
        attr_set = true;
    }

    k_init<<<KCODES, DIM>>>(embed);
    k_gemm<<<(unsigned)(N / MROWS), 256, SMEM_TOTAL>>>(x, embed, out, indOff);
    k_fixup<<<256, 256>>>(x, embed, out, indOff);
    k_final1<<<1, KCODES>>>(cs, out, ncsOff);
    k_final2<<<KCODES * DIM / 256, 256>>>(ea, out, neaOff, neOff);
}

// round 17
// speedup vs baseline: 2.8766x; 1.2204x over previous
#include <cuda_runtime.h>
#include <cuda_bf16.h>
#include <cstdint>

// Shapes fixed by the reference: x [8,8192,128], embed [1024,128]
#define DIM     128
#define KCODES  1024
#define NROWS   65536
#define MROWS   128          // rows per gemm block
#define NT      64           // codes per tile
#define NTILES  (KCODES/NT)  // 16
#define TAU     0.4f         // top-2 gap below which row goes to exact fixup (8 sigma)

#define ASTR    136          // padded row stride in bf16 (272 B = 4-bank shift/row)
#define SM_A    0
#define A_BYTES (MROWS*ASTR*2)            // 34816
#define SM_B0   (A_BYTES)
#define B_BYTES (NT*ASTR*2)               // 17408
#define SM_B1   (SM_B0 + B_BYTES)
#define SM_EN   (SM_B1 + B_BYTES)         // 69632
#define SM_RED  (SM_EN + KCODES*4)        // 73728 : redS|redI|redS2 (3 KB)
#define SM_BEST (SM_RED + 3072)           // 76800 : per-row best idx (512 B)
#define SM_CONF (SM_BEST + 512)           // 77312 : per-row confident flag
#define SMEM_TOTAL (SM_CONF + 512)        // 77824 B = 76 KB -> 3 blocks/SM (exactly 228 KB)

static const float DECAY_F = 0.99f;
static const float OMD_F   = (float)(1.0 - 0.99);
static const float EPS_F   = 1e-5f;

// ---- device scratch (no cudaMalloc allowed) ----
__device__ float g_counts[KCODES];
__device__ float g_sums[KCODES * DIM];
__device__ float g_enorm[KCODES];
__device__ __align__(16) __nv_bfloat16 g_e1[KCODES * DIM];   // bf16(embed)
__device__ int g_fix[NROWS];
__device__ int g_fix_cnt;

// ---------------------------------------------------------------------------
__device__ __forceinline__ uint32_t smem_u32(const void* p) {
    uint32_t a;
    asm("{ .reg .u64 t; cvta.to.shared.u64 t, %1; cvt.u32.u64 %0, t; }" : "=r"(a) : "l"(p));
    return a;
}
__device__ __forceinline__ void cp16(uint32_t dst, const void* src) {
    asm volatile("cp.async.cg.shared.global [%0], [%1], 16;" :: "r"(dst), "l"(src) : "memory");
}
#define CP_COMMIT() asm volatile("cp.async.commit_group;" ::: "memory")
#define CP_WAIT(n)  asm volatile("cp.async.wait_group %0;" :: "n"(n) : "memory")

// mma.sync m16n8k16 bf16 (sm_80+ PTX, valid at base sm_103 target)
__device__ __forceinline__ void mma16816(float* c, const uint32_t* a, const uint32_t* b) {
    asm volatile(
        "mma.sync.aligned.m16n8k16.row.col.f32.bf16.bf16.f32 "
        "{%0,%1,%2,%3}, {%4,%5,%6,%7}, {%8,%9}, {%0,%1,%2,%3};"
        : "+f"(c[0]), "+f"(c[1]), "+f"(c[2]), "+f"(c[3])
        : "r"(a[0]), "r"(a[1]), "r"(a[2]), "r"(a[3]), "r"(b[0]), "r"(b[1]));
}

// ---------------------------------------------------------------------------
// k_init: enorm (fp32 exact), zero scratch, embed -> bf16
// ---------------------------------------------------------------------------
__global__ void k_init(const float* __restrict__ embed) {
    int k = blockIdx.x, t = threadIdx.x;
    float v = embed[k * DIM + t];
    float p = v * v;
#pragma unroll
    for (int off = 16; off > 0; off >>= 1) p += __shfl_down_sync(0xffffffffu, p, off);
    __shared__ float s[4];
    if ((t & 31) == 0) s[t >> 5] = p;
    __syncthreads();
    if (t == 0) { g_enorm[k] = s[0] + s[1] + s[2] + s[3]; g_counts[k] = 0.0f; }
    if (k == 0 && t == 0) g_fix_cnt = 0;
    g_sums[(size_t)k * DIM + t] = 0.0f;
    g_e1[k * DIM + t] = __float2bfloat16(v);
}

// ---------------------------------------------------------------------------
// k_gemm: bf16 mma.sync distance GEMM (K=128) + top-2 argmax + confident scatter
// 512 blocks x 256 thr, 3 blocks/SM. Warp (wm 0..3, wn 0..1): rows wm*32..+31,
// codes wn*32..+31 per 64-code tile. A resident smem, B double-buffer cp.async.
// ---------------------------------------------------------------------------
__global__ __launch_bounds__(256, 3)
void k_gemm(const float* __restrict__ x, const float* __restrict__ embed,
            float* __restrict__ out, long long indOff) {
    extern __shared__ unsigned char sm[];
    __nv_bfloat16* As = (__nv_bfloat16*)(sm + SM_A);
    float* enorm_s = (float*)(sm + SM_EN);
    float* redS  = (float*)(sm + SM_RED);
    int*   redI  = (int*)(sm + SM_RED + 1024);
    float* redS2 = (float*)(sm + SM_RED + 2048);
    int*   best_s = (int*)(sm + SM_BEST);
    int*   conf_s = (int*)(sm + SM_CONF);

    const int tid  = threadIdx.x;
    const int lane = tid & 31;
    const int wid  = tid >> 5;
    const int wm   = wid >> 1;
    const int wn   = wid & 1;
    const long long rowBase = (long long)blockIdx.x * MROWS;

#pragma unroll
    for (int m = 0; m < 4; m++)
        enorm_s[tid + m * 256] = g_enorm[tid + m * 256];

    // A: x [128 x 128] f32 -> bf16 rows (stride ASTR)
    {
        const float4* xg = (const float4*)(x + rowBase * DIM);
#pragma unroll
        for (int m = 0; m < 16; m++) {
            int flat = tid + m * 256;           // 4096 float4
            int r = flat >> 5, c4 = flat & 31;
            float4 v = xg[flat];
            union { __nv_bfloat16 h[4]; unsigned long long u; } H;
            H.h[0] = __float2bfloat16(v.x);
            H.h[1] = __float2bfloat16(v.y);
            H.h[2] = __float2bfloat16(v.z);
            H.h[3] = __float2bfloat16(v.w);
            *(unsigned long long*)(As + (size_t)r * ASTR + c4 * 4) = H.u;
        }
    }

    const uint32_t smb = smem_u32(sm);
#define PREFETCH_B(t, buf) do {                                               \
        const __nv_bfloat16* eb = g_e1 + (size_t)(t) * NT * DIM;              \
        uint32_t sb = smb + ((buf) ? SM_B1 : SM_B0);                          \
        _Pragma("unroll")                                                     \
        for (int m = 0; m < 4; m++) {                                         \
            int flat = tid + m * 256;        /* 1024 chunks of 16 B */        \
            int r = flat >> 4, ch = flat & 15;                                \
            cp16(sb + (uint32_t)(r * (ASTR * 2) + ch * 16),                   \
                 eb + (size_t)r * DIM + ch * 8);                              \
        }                                                                     \
        CP_COMMIT();                                                          \
    } while (0)

    PREFETCH_B(0, 0);

    const uint32_t aoff  = (uint32_t)((wm * 32 + (lane >> 2)) * ASTR + (lane & 3) * 2);
    const uint32_t boff0 = (uint32_t)((lane >> 2) * ASTR + (lane & 3) * 2);

    float bs[2][2], ss[2][2];
    int   bi[2][2];
#pragma unroll
    for (int a = 0; a < 2; a++)
#pragma unroll
        for (int b = 0; b < 2; b++) { bs[a][b] = -3.4e38f; ss[a][b] = -3.4e38f; bi[a][b] = 0; }

    __syncthreads();

    for (int t = 0; t < NTILES; t++) {
        if (t + 1 < NTILES) { PREFETCH_B(t + 1, (t + 1) & 1); CP_WAIT(1); }
        else                { CP_WAIT(0); }
        __syncthreads();

        const __nv_bfloat16* Bs = (const __nv_bfloat16*)(sm + ((t & 1) ? SM_B1 : SM_B0));

        float acc[2][4][4];
#pragma unroll
        for (int mi = 0; mi < 2; mi++)
#pragma unroll
            for (int ni = 0; ni < 4; ni++)
#pragma unroll
                for (int e = 0; e < 4; e++) acc[mi][ni][e] = 0.0f;

#pragma unroll
        for (int ks = 0; ks < DIM / 16; ks++) {
            const int k0 = ks * 16;
            uint32_t a[2][4], b[4][2];
#pragma unroll
            for (int mi = 0; mi < 2; mi++) {
                uint32_t base = aoff + mi * (16 * ASTR) + k0;
                a[mi][0] = *(const uint32_t*)(As + base);
                a[mi][1] = *(const uint32_t*)(As + base + 8 * ASTR);
                a[mi][2] = *(const uint32_t*)(As + base + 8);
                a[mi][3] = *(const uint32_t*)(As + base + 8 * ASTR + 8);
            }
#pragma unroll
            for (int ni = 0; ni < 4; ni++) {
                uint32_t base = boff0 + (uint32_t)((wn * 32 + ni * 8) * ASTR) + k0;
                b[ni][0] = *(const uint32_t*)(Bs + base);
                b[ni][1] = *(const uint32_t*)(Bs + base + 8);
            }
#pragma unroll
            for (int mi = 0; mi < 2; mi++)
#pragma unroll
                for (int ni = 0; ni < 4; ni++)
                    mma16816(acc[mi][ni], a[mi], b[ni]);
        }

        const int cb = t * NT + wn * 32 + (lane & 3) * 2;
#pragma unroll
        for (int ni = 0; ni < 4; ni++) {
            const int c0 = cb + ni * 8;
            const float e0 = enorm_s[c0], e1 = enorm_s[c0 + 1];
#pragma unroll
            for (int mi = 0; mi < 2; mi++) {
#pragma unroll
                for (int rh = 0; rh < 2; rh++) {
                    float s0 = fmaf(acc[mi][ni][rh * 2 + 0], 2.0f, -e0);
                    float s1 = fmaf(acc[mi][ni][rh * 2 + 1], 2.0f, -e1);
                    if (s0 > ss[mi][rh]) {
                        if (s0 > bs[mi][rh]) { ss[mi][rh] = bs[mi][rh]; bs[mi][rh] = s0; bi[mi][rh] = c0; }
                        else ss[mi][rh] = s0;
                    }
                    if (s1 > ss[mi][rh]) {
                        if (s1 > bs[mi][rh]) { ss[mi][rh] = bs[mi][rh]; bs[mi][rh] = s1; bi[mi][rh] = c0 + 1; }
                        else ss[mi][rh] = s1;
                    }
                }
            }
        }
        __syncthreads();
    }

    // merge across the 4 lanes of each quad (same rows)
#pragma unroll
    for (int off = 1; off <= 2; off <<= 1) {
#pragma unroll
        for (int mi = 0; mi < 2; mi++)
#pragma unroll
            for (int rh = 0; rh < 2; rh++) {
                float obs = __shfl_xor_sync(0xffffffffu, bs[mi][rh], off);
                int   obi = __shfl_xor_sync(0xffffffffu, bi[mi][rh], off);
                float oss = __shfl_xor_sync(0xffffffffu, ss[mi][rh], off);
                float loser = fminf(bs[mi][rh], obs);
                float nss = fmaxf(loser, fmaxf(ss[mi][rh], oss));
                if (obs > bs[mi][rh] || (obs == bs[mi][rh] && obi < bi[mi][rh])) {
                    bs[mi][rh] = obs; bi[mi][rh] = obi;
                }
                ss[mi][rh] = nss;
            }
    }
    if ((lane & 3) == 0) {
#pragma unroll
        for (int mi = 0; mi < 2; mi++)
#pragma unroll
            for (int rh = 0; rh < 2; rh++) {
                int r = wm * 32 + mi * 16 + rh * 8 + (lane >> 2);
                redS[r * 2 + wn]  = bs[mi][rh];
                redI[r * 2 + wn]  = bi[mi][rh];
                redS2[r * 2 + wn] = ss[mi][rh];
            }
    }
    __syncthreads();
    if (tid < MROWS) {
        float b0 = redS[tid * 2], b1 = redS[tid * 2 + 1];
        int   i0 = redI[tid * 2], i1 = redI[tid * 2 + 1];
        float s0 = redS2[tid * 2], s1 = redS2[tid * 2 + 1];
        float sec  = fmaxf(fminf(b0, b1), fmaxf(s0, s1));
        float best = b0; int bidx = i0;
        if (b1 > b0 || (b1 == b0 && i1 < i0)) { best = b1; bidx = i1; }
        int conf = (best - sec) >= TAU;
        best_s[tid] = bidx;
        conf_s[tid] = conf;
        if (conf) {
            out[indOff + rowBase + tid] = (float)bidx;
            atomicAdd(&g_counts[bidx], 1.0f);
        } else {
            int p = atomicAdd(&g_fix_cnt, 1);
            g_fix[p] = (int)(rowBase + tid);
        }
    }
    __syncthreads();

    // confident-row scatter: quantize gather + segment-sum atomics
#pragma unroll
    for (int m = 0; m < 16; m++) {
        int flat = tid + m * 256;
        int r = flat >> 5, c = flat & 31;
        if (conf_s[r]) {
            int best = best_s[r];
            float4 e4 = ((const float4*)(embed + (size_t)best * DIM))[c];
            ((float4*)(out + (rowBase + r) * DIM))[c] = e4;
            float4 xv = ((const float4*)(x + (rowBase + r) * DIM))[c];
            float* sp = g_sums + (size_t)best * DIM + c * 4;
            atomicAdd(sp + 0, xv.x);
            atomicAdd(sp + 1, xv.y);
            atomicAdd(sp + 2, xv.z);
            atomicAdd(sp + 3, xv.w);
        }
    }
}

// ---------------------------------------------------------------------------
// k_fixup: exact fp32 argmax + scatter for ambiguous rows. 32 rows per block
// chunk, embed streamed via smem in 32-code tiles (tiled fp32 GEMM).
// ---------------------------------------------------------------------------
__global__ __launch_bounds__(256) void k_fixup(const float* __restrict__ x,
                                               const float* __restrict__ embed,
                                               float* __restrict__ out,
                                               long long indOff) {
    __shared__ float4 xs[32][33];
    __shared__ float4 es[32][33];
    __shared__ float  en_s[KCODES];
    __shared__ int    rowIds[32];
    __shared__ int    sIdx[32];

    const int tid = threadIdx.x;
    const int tx = tid & 15, ty = tid >> 4;
#pragma unroll
    for (int m = 0; m < 4; m++) en_s[tid + m * 256] = g_enorm[tid + m * 256];

    int cnt = g_fix_cnt;
    for (int base = blockIdx.x * 32; base < cnt; base += gridDim.x * 32) {
        int nrows = min(32, cnt - base);
        if (tid < nrows) rowIds[tid] = g_fix[base + tid];
        __syncthreads();
#pragma unroll
        for (int m = 0; m < 4; m++) {
            int idx = tid + m * 256;
            int r = idx >> 5, c = idx & 31;
            if (r < nrows)
                xs[r][c] = ((const float4*)(x + (size_t)rowIds[r] * DIM))[c];
        }

        float best[2] = {-3.4e38f, -3.4e38f};
        int   bidx[2] = {0, 0};

        for (int tile = 0; tile < KCODES / 32; tile++) {
            __syncthreads();
#pragma unroll
            for (int m = 0; m < 4; m++) {
                int idx = tid + m * 256;
                int r = idx >> 5, c = idx & 31;
                es[r][c] = ((const float4*)(embed + (size_t)(tile * 32 + r) * DIM))[c];
            }
            __syncthreads();

            float acc[2][2] = {{0.f, 0.f}, {0.f, 0.f}};
#pragma unroll 8
            for (int c4 = 0; c4 < 32; c4++) {
                float4 a0 = xs[ty][c4],      a1 = xs[ty + 16][c4];
                float4 b0 = es[tx][c4],      b1 = es[tx + 16][c4];
                acc[0][0] = fmaf(a0.x, b0.x, fmaf(a0.y, b0.y, fmaf(a0.z, b0.z, fmaf(a0.w, b0.w, acc[0][0]))));
                acc[0][1] = fmaf(a0.x, b1.x, fmaf(a0.y, b1.y, fmaf(a0.z, b1.z, fmaf(a0.w, b1.w, acc[0][1]))));
                acc[1][0] = fmaf(a1.x, b0.x, fmaf(a1.y, b0.y, fmaf(a1.z, b0.z, fmaf(a1.w, b0.w, acc[1][0]))));
                acc[1][1] = fmaf(a1.x, b1.x, fmaf(a1.y, b1.y, fmaf(a1.z, b1.z, fmaf(a1.w, b1.w, acc[1][1]))));
            }
#pragma unroll
            for (int j = 0; j < 2; j++) {
                int code = tile * 32 + tx + j * 16;
                float e = en_s[code];
#pragma unroll
                for (int i = 0; i < 2; i++) {
                    float sc = 2.0f * acc[i][j] - e;
                    if (sc > best[i] || (sc == best[i] && code < bidx[i])) {
                        best[i] = sc; bidx[i] = code;
                    }
                }
            }
        }
#pragma unroll
        for (int i = 0; i < 2; i++) {
            float s = best[i]; int idx = bidx[i];
#pragma unroll
            for (int off = 8; off > 0; off >>= 1) {
                float so = __shfl_down_sync(0xffffffffu, s, off, 16);
                int   io = __shfl_down_sync(0xffffffffu, idx, off, 16);
                if (so > s || (so == s && io < idx)) { s = so; idx = io; }
            }
            if (tx == 0) sIdx[ty + i * 16] = idx;
        }
        __syncthreads();

#pragma unroll
        for (int m = 0; m < 4; m++) {
            int idx = tid + m * 256;
            int r = idx >> 5, c = idx & 31;
            if (r < nrows) {
                int bestc = sIdx[r];
                long long row = rowIds[r];
                float4 e4 = ((const float4*)(embed + (size_t)bestc * DIM))[c];
                ((float4*)(out + row * DIM))[c] = e4;
                float4 xv = xs[r][c];
                float* sp = g_sums + (size_t)bestc * DIM + c * 4;
                atomicAdd(sp + 0, xv.x);
                atomicAdd(sp + 1, xv.y);
                atomicAdd(sp + 2, xv.z);
                atomicAdd(sp + 3, xv.w);
            }
        }
        if (tid < nrows) {
            int bestc = sIdx[tid];
            atomicAdd(&g_counts[bestc], 1.0f);
            out[indOff + rowIds[tid]] = (float)bestc;
        }
        __syncthreads();
    }
}

// ---------------------------------------------------------------------------
// k_final: fused EMA epilogue. total = 0.99*sum(cs) + 0.01*65536 (sum(counts)
// is exactly N). Each block reduces sum(cs) itself (1024 floats, L2-hot),
// then handles 256 elements of embed_avg/new_embed + one ncs write per code.
// ---------------------------------------------------------------------------
__global__ __launch_bounds__(256) void k_final(const float* __restrict__ cs,
                                               const float* __restrict__ ea,
                                               float* __restrict__ out,
                                               long long ncsOff, long long neaOff,
                                               long long neOff) {
    __shared__ float red[8];
    const int tid = threadIdx.x;
    float s = cs[tid] + cs[tid + 256] + cs[tid + 512] + cs[tid + 768];
#pragma unroll
    for (int off = 16; off > 0; off >>= 1) s += __shfl_down_sync(0xffffffffu, s, off);
    if ((tid & 31) == 0) red[tid >> 5] = s;
    __syncthreads();
    float total;
    {
        float t0 = red[0] + red[1] + red[2] + red[3] + red[4] + red[5] + red[6] + red[7];
        total = t0 * DECAY_F + OMD_F * (float)NROWS;
    }
    long long i = (long long)blockIdx.x * 256 + tid;
    int code = (int)(i >> 7);
    float ncs = cs[code] * DECAY_F + OMD_F * g_counts[code];
    float nea = ea[i] * DECAY_F + OMD_F * g_sums[i];
    out[neaOff + i] = nea;
    float smoothed_counts = (ncs + EPS_F) / (total + (float)KCODES * EPS_F) * total;
    out[neOff + i] = nea / smoothed_counts;
    if ((i & 127) == 0) out[ncsOff + code] = ncs;
}

// ---------------------------------------------------------------------------
extern "C" void kernel_launch(void* const* d_in, const int* in_sizes, int n_in,
                              void* d_out, int out_size) {
    const float* x     = (const float*)d_in[0];
    const float* embed = (const float*)d_in[1];
    const float* cs    = (const float*)d_in[2];
    const float* ea    = (const float*)d_in[3];
    float* out = (float*)d_out;

    const long long N = in_sizes[0] / DIM;            // 65536 rows
    const long long indOff = N * DIM;
    const long long ncsOff = indOff + N;
    const long long neaOff = ncsOff + KCODES;
    const long long neOff  = neaOff + (long long)KCODES * DIM;

    static bool attr_set = false;
    if (!attr_set) {
        cudaFuncSetAttribute(k_gemm, cudaFuncAttributeMaxDynamicSharedMemorySize, SMEM_TOTAL);
        attr_set = true;
    }

    k_init<<<KCODES, DIM>>>(embed);
    k_gemm<<<(unsigned)(N / MROWS), 256, SMEM_TOTAL>>>(x, embed, out, indOff);
    k_fixup<<<256, 256>>>(x, embed, out, indOff);
    k_final<<<KCODES * DIM / 256, 256>>>(cs, ea, out, ncsOff, neaOff, neOff);
}